// round 1
// baseline (speedup 1.0000x reference)
#include <cuda_runtime.h>
#include <cstdint>

// Problem constants
#define D_MODEL   1024
#define NUM_HEADS 16
#define DEPTH     64
#define BATCH     4
#define SEQ       2048
#define ROWS_TOT  (BATCH * SEQ)   // 8192
#define ATT_SCALE 0.125f          // 1/sqrt(DEPTH)

// ---------------------------------------------------------------------------
// Scratch (device globals -- no allocation allowed)
// ---------------------------------------------------------------------------
__device__ float g_qp[ROWS_TOT * D_MODEL];
__device__ float g_kp[ROWS_TOT * D_MODEL];
__device__ float g_vp[ROWS_TOT * D_MODEL];
__device__ float g_op[ROWS_TOT * D_MODEL];

// ---------------------------------------------------------------------------
// Packed f32x2 helpers (Blackwell sm_100+: doubles FFMA throughput)
// ---------------------------------------------------------------------------
__device__ __forceinline__ unsigned long long pack2(float x, float y) {
    unsigned long long r;
    asm("mov.b64 %0, {%1, %2};" : "=l"(r) : "f"(x), "f"(y));
    return r;
}
__device__ __forceinline__ float2 unpack2(unsigned long long u) {
    float2 f;
    asm("mov.b64 {%0, %1}, %2;" : "=f"(f.x), "=f"(f.y) : "l"(u));
    return f;
}
__device__ __forceinline__ unsigned long long fma2(unsigned long long a,
                                                   unsigned long long b,
                                                   unsigned long long c) {
    unsigned long long d;
    asm("fma.rn.f32x2 %0, %1, %2, %3;" : "=l"(d) : "l"(a), "l"(b), "l"(c));
    return d;
}
__device__ __forceinline__ unsigned long long mul2(unsigned long long a,
                                                   unsigned long long b) {
    unsigned long long d;
    asm("mul.rn.f32x2 %0, %1, %2;" : "=l"(d) : "l"(a), "l"(b));
    return d;
}

// ---------------------------------------------------------------------------
// GEMM: Y[m,n] = sum_k X[m,k] * W[n,k] + bias[n]     (x @ W.T + b)
// M = 8192, N = K = 1024. Tiles: 64x64x16, 256 threads, 4x4 micro-tile,
// f32x2 pairs along n (WsT transposed so column pairs are contiguous).
// ---------------------------------------------------------------------------
#define GBM 64
#define GBN 64
#define GBK 16

__global__ __launch_bounds__(256) void gemm_bias_kernel(
    const float* __restrict__ X, const float* __restrict__ W,
    const float* __restrict__ bias, float* __restrict__ Y)
{
    __shared__ __align__(16) float Xs[GBM][GBK];        // natural [m][k]
    __shared__ __align__(16) float WsT[GBK][GBN + 4];   // transposed [k][n], pad 68

    const int tid = threadIdx.x;
    const int tx = tid & 15;         // 0..15 -> n micro (4 cols)
    const int ty = tid >> 4;         // 0..15 -> m micro (4 rows)
    const int n0 = blockIdx.x * GBN;
    const int m0 = blockIdx.y * GBM;

    const int lrow = tid >> 2;           // 0..63
    const int lc4  = (tid & 3) << 2;     // 0,4,8,12

    unsigned long long acc[4][2];
#pragma unroll
    for (int i = 0; i < 4; i++) { acc[i][0] = 0ull; acc[i][1] = 0ull; }

    for (int kt = 0; kt < D_MODEL; kt += GBK) {
        float4 xv = *(const float4*)&X[(size_t)(m0 + lrow) * D_MODEL + kt + lc4];
        float4 wv = *(const float4*)&W[(size_t)(n0 + lrow) * D_MODEL + kt + lc4];
        *(float4*)&Xs[lrow][lc4] = xv;
        WsT[lc4 + 0][lrow] = wv.x;
        WsT[lc4 + 1][lrow] = wv.y;
        WsT[lc4 + 2][lrow] = wv.z;
        WsT[lc4 + 3][lrow] = wv.w;
        __syncthreads();

#pragma unroll
        for (int kk = 0; kk < GBK; kk++) {
            const ulonglong2 b2 = *(const ulonglong2*)&WsT[kk][tx << 2];
#pragma unroll
            for (int i = 0; i < 4; i++) {
                const float a = Xs[(ty << 2) + i][kk];
                const unsigned long long aa = pack2(a, a);
                acc[i][0] = fma2(aa, b2.x, acc[i][0]);
                acc[i][1] = fma2(aa, b2.y, acc[i][1]);
            }
        }
        __syncthreads();
    }

    const float4 bv = *(const float4*)&bias[n0 + (tx << 2)];
#pragma unroll
    for (int i = 0; i < 4; i++) {
        const float2 lo = unpack2(acc[i][0]);
        const float2 hi = unpack2(acc[i][1]);
        float4 o = make_float4(lo.x + bv.x, lo.y + bv.y, hi.x + bv.z, hi.y + bv.w);
        *(float4*)&Y[(size_t)(m0 + (ty << 2) + i) * D_MODEL + n0 + (tx << 2)] = o;
    }
}

// ---------------------------------------------------------------------------
// Fused attention (flash style). One block = 64 queries x 1 head.
// KV streamed in 32-row tiles with online softmax. fp32 + f32x2.
// Heads are column slices of the projected [B*S, D_MODEL] buffers.
// ---------------------------------------------------------------------------
#define AQ 64
#define AK 32

__global__ __launch_bounds__(256) void attn_kernel(
    const float* __restrict__ Q, const float* __restrict__ K,
    const float* __restrict__ V, float* __restrict__ O)
{
    __shared__ __align__(16) float QsT[DEPTH][AQ + 4];   // [d][row], pad 68
    __shared__ __align__(16) float Ks [AK][DEPTH + 1];   // [kv][d],  pad 65
    __shared__ __align__(16) float Vs [AK][DEPTH];       // [kv][d]
    __shared__ __align__(16) float Ps [AQ][AK];          // [row][kv]

    const int tid = threadIdx.x;
    const int tx = tid & 15;     // scores: 2 cols (2tx, 2tx+1) | PV: 4 depth cols
    const int ty = tid >> 4;     // 4 query rows (4ty .. 4ty+3)
    const int q0 = blockIdx.x * AQ;
    const int h  = blockIdx.y;
    const int b  = blockIdx.z;
    const size_t base = ((size_t)b * SEQ) * D_MODEL + (size_t)h * DEPTH;

    // Load Q tile (64x64), scaled, transposed -> QsT[d][row]
#pragma unroll
    for (int it = 0; it < 4; it++) {
        const int idx = tid + (it << 8);
        const int r  = idx >> 4;
        const int c4 = (idx & 15) << 2;
        float4 v4 = *(const float4*)&Q[base + (size_t)(q0 + r) * D_MODEL + c4];
        QsT[c4 + 0][r] = v4.x * ATT_SCALE;
        QsT[c4 + 1][r] = v4.y * ATT_SCALE;
        QsT[c4 + 2][r] = v4.z * ATT_SCALE;
        QsT[c4 + 3][r] = v4.w * ATT_SCALE;
    }

    float m_[4], l_[4];
    unsigned long long accO[4][2];
#pragma unroll
    for (int i = 0; i < 4; i++) {
        m_[i] = -3.0e38f; l_[i] = 0.0f;
        accO[i][0] = 0ull; accO[i][1] = 0ull;
    }

    for (int t = 0; t < SEQ / AK; t++) {
        const int kv0 = t * AK;
        __syncthreads();   // prev-iter PV done reading Ks/Vs; QsT visible at t=0

        // Load K (scalar, padded) and V (vectorized) tiles: 32 x 64
#pragma unroll
        for (int it = 0; it < 2; it++) {
            const int idx = tid + (it << 8);
            const int r  = idx >> 4;
            const int c4 = (idx & 15) << 2;
            float4 k4 = *(const float4*)&K[base + (size_t)(kv0 + r) * D_MODEL + c4];
            Ks[r][c4 + 0] = k4.x; Ks[r][c4 + 1] = k4.y;
            Ks[r][c4 + 2] = k4.z; Ks[r][c4 + 3] = k4.w;
            float4 v4 = *(const float4*)&V[base + (size_t)(kv0 + r) * D_MODEL + c4];
            *(float4*)&Vs[r][c4] = v4;
        }
        __syncthreads();

        // Scores: rows 4ty..4ty+3 (as 2 row-pairs), cols 2tx, 2tx+1
        unsigned long long s00 = 0ull, s01 = 0ull, s10 = 0ull, s11 = 0ull;
#pragma unroll 16
        for (int kk = 0; kk < DEPTH; kk++) {
            const ulonglong2 qa = *(const ulonglong2*)&QsT[kk][ty << 2];
            const float b0 = Ks[(tx << 1) + 0][kk];
            const float b1 = Ks[(tx << 1) + 1][kk];
            const unsigned long long bb0 = pack2(b0, b0);
            const unsigned long long bb1 = pack2(b1, b1);
            s00 = fma2(qa.x, bb0, s00); s01 = fma2(qa.y, bb0, s01);
            s10 = fma2(qa.x, bb1, s10); s11 = fma2(qa.y, bb1, s11);
        }
        float sc[4][2];
        { float2 f = unpack2(s00); sc[0][0] = f.x; sc[1][0] = f.y; }
        { float2 f = unpack2(s01); sc[2][0] = f.x; sc[3][0] = f.y; }
        { float2 f = unpack2(s10); sc[0][1] = f.x; sc[1][1] = f.y; }
        { float2 f = unpack2(s11); sc[2][1] = f.x; sc[3][1] = f.y; }

        // Online softmax update (per query row; stats reduced over the 16
        // tx-lanes of each row group via xor-shuffles, offsets < 16)
#pragma unroll
        for (int i = 0; i < 4; i++) {
            float tm = fmaxf(sc[i][0], sc[i][1]);
#pragma unroll
            for (int o = 8; o; o >>= 1)
                tm = fmaxf(tm, __shfl_xor_sync(0xffffffffu, tm, o));
            const float mn   = fmaxf(m_[i], tm);
            const float corr = __expf(m_[i] - mn);
            m_[i] = mn;
            const float p0 = __expf(sc[i][0] - mn);
            const float p1 = __expf(sc[i][1] - mn);
            float ts = p0 + p1;
#pragma unroll
            for (int o = 8; o; o >>= 1)
                ts += __shfl_xor_sync(0xffffffffu, ts, o);
            l_[i] = l_[i] * corr + ts;
            const unsigned long long cc = pack2(corr, corr);
            accO[i][0] = mul2(accO[i][0], cc);
            accO[i][1] = mul2(accO[i][1], cc);
            *(float2*)&Ps[(ty << 2) + i][tx << 1] = make_float2(p0, p1);
        }
        __syncthreads();   // Ps visible to everyone

        // PV: accO[row i][depth cols 4tx..4tx+3] += P[row][kc] * V[kc][col]
#pragma unroll 8
        for (int kc = 0; kc < AK; kc++) {
            const ulonglong2 vv = *(const ulonglong2*)&Vs[kc][tx << 2];
#pragma unroll
            for (int i = 0; i < 4; i++) {
                const float a = Ps[(ty << 2) + i][kc];
                const unsigned long long aa = pack2(a, a);
                accO[i][0] = fma2(aa, vv.x, accO[i][0]);
                accO[i][1] = fma2(aa, vv.y, accO[i][1]);
            }
        }
    }

    // Epilogue: normalize and write O in [B,S,H*depth] layout
#pragma unroll
    for (int i = 0; i < 4; i++) {
        const float inv = 1.0f / l_[i];
        const float2 lo = unpack2(accO[i][0]);
        const float2 hi = unpack2(accO[i][1]);
        float4 o4 = make_float4(lo.x * inv, lo.y * inv, hi.x * inv, hi.y * inv);
        *(float4*)&O[base + (size_t)(q0 + (ty << 2) + i) * D_MODEL + (tx << 2)] = o4;
    }
}

// ---------------------------------------------------------------------------
// Launch: 3 projections -> fused attention -> dense
// Input order (metadata): v, k, q, wq_w, wq_b, wk_w, wk_b, wv_w, wv_b,
//                          dense_w, dense_b
// ---------------------------------------------------------------------------
extern "C" void kernel_launch(void* const* d_in, const int* in_sizes, int n_in,
                              void* d_out, int out_size)
{
    (void)in_sizes; (void)n_in; (void)out_size;
    const float* v_in = (const float*)d_in[0];
    const float* k_in = (const float*)d_in[1];
    const float* q_in = (const float*)d_in[2];
    const float* wq   = (const float*)d_in[3];
    const float* bq   = (const float*)d_in[4];
    const float* wk   = (const float*)d_in[5];
    const float* bk   = (const float*)d_in[6];
    const float* wv   = (const float*)d_in[7];
    const float* bv   = (const float*)d_in[8];
    const float* wd   = (const float*)d_in[9];
    const float* bd   = (const float*)d_in[10];

    float *pq, *pk, *pv, *po;
    cudaGetSymbolAddress((void**)&pq, g_qp);
    cudaGetSymbolAddress((void**)&pk, g_kp);
    cudaGetSymbolAddress((void**)&pv, g_vp);
    cudaGetSymbolAddress((void**)&po, g_op);

    dim3 ggrid(D_MODEL / GBN, ROWS_TOT / GBM);   // (16, 128)
    gemm_bias_kernel<<<ggrid, 256>>>(q_in, wq, bq, pq);
    gemm_bias_kernel<<<ggrid, 256>>>(k_in, wk, bk, pk);
    gemm_bias_kernel<<<ggrid, 256>>>(v_in, wv, bv, pv);

    attn_kernel<<<dim3(SEQ / AQ, NUM_HEADS, BATCH), 256>>>(pq, pk, pv, po);

    gemm_bias_kernel<<<ggrid, 256>>>(po, wd, bd, (float*)d_out);
}

// round 4
// speedup vs baseline: 1.1844x; 1.1844x over previous
#include <cuda_runtime.h>
#include <mma.h>
#include <cstdint>

using namespace nvcuda;

// Problem constants
#define D_MODEL   1024
#define NUM_HEADS 16
#define DEPTH     64
#define BATCH     4
#define SEQ       2048
#define ROWS_TOT  (BATCH * SEQ)   // 8192
#define ATT_SCALE 0.125f          // 1/sqrt(DEPTH)

// ---------------------------------------------------------------------------
// Scratch (device globals -- no allocation allowed)
// ---------------------------------------------------------------------------
__device__ float g_qp[ROWS_TOT * D_MODEL];
__device__ float g_kp[ROWS_TOT * D_MODEL];
__device__ float g_vp[ROWS_TOT * D_MODEL];
__device__ float g_op[ROWS_TOT * D_MODEL];
__device__ float g_xc[ROWS_TOT * D_MODEL];   // tf32-rounded activations
__device__ float g_wc[D_MODEL * D_MODEL];    // tf32-rounded weights

// ---------------------------------------------------------------------------
// tf32-rna rounding pass (unbiased tf32 conversion, stored as fp32)
// ---------------------------------------------------------------------------
__global__ void rna_tf32_kernel(const float4* __restrict__ x, float4* __restrict__ y) {
    const int i = blockIdx.x * blockDim.x + threadIdx.x;
    float4 v = x[i];
    uint32_t a, b, c, d;
    asm("cvt.rna.tf32.f32 %0, %1;" : "=r"(a) : "f"(v.x));
    asm("cvt.rna.tf32.f32 %0, %1;" : "=r"(b) : "f"(v.y));
    asm("cvt.rna.tf32.f32 %0, %1;" : "=r"(c) : "f"(v.z));
    asm("cvt.rna.tf32.f32 %0, %1;" : "=r"(d) : "f"(v.w));
    float4 o;
    o.x = __uint_as_float(a); o.y = __uint_as_float(b);
    o.z = __uint_as_float(c); o.w = __uint_as_float(d);
    y[i] = o;
}

// ---------------------------------------------------------------------------
// wmma tf32 GEMM: Y[m,n] = sum_k X[m,k] * W[n,k] + bias[n]   (x @ W.T + b)
// CTA tile 128x128, K-tile 32, 3-stage cp.async pipeline.
// 8 warps in 4(M) x 2(N); warp tile 32x64 = 2x4 wmma m16n16k8 fragments.
// ---------------------------------------------------------------------------
#define KTILE     32
#define LDA       36                       // 32 + 4 pad (rows stay 16B aligned)
#define STG_FLT   (2 * 128 * LDA)          // floats per stage (A + B) = 9216
#define STG_BYTES (STG_FLT * 4)            // 36864
#define NSTAGE    3
#define GEMM_SMEM (512 + NSTAGE * STG_BYTES)   // bias + stages = 111104

#define CP_ASYNC16(dst, src) \
    asm volatile("cp.async.cg.shared.global [%0], [%1], 16;" :: "r"(dst), "l"(src) : "memory")
#define CP_COMMIT()  asm volatile("cp.async.commit_group;" ::: "memory")
#define CP_WAIT2()   asm volatile("cp.async.wait_group 2;" ::: "memory")

__device__ __forceinline__ uint32_t smem_u32(const void* p) {
    uint32_t a;
    asm("{ .reg .u64 t; cvta.to.shared.u64 t, %1; cvt.u32.u64 %0, t; }"
        : "=r"(a) : "l"(p));
    return a;
}

__global__ __launch_bounds__(256) void gemm_wmma_tf32_kernel(
    const float* __restrict__ X, const float* __restrict__ W,
    const float* __restrict__ bias, float* __restrict__ Y)
{
    extern __shared__ char smem[];
    float* bs   = (float*)smem;                 // 128 bias floats (512 B)
    float* tile = (float*)(smem + 512);         // staged A/B tiles

    const int tid   = threadIdx.x;
    const int wid   = tid >> 5;
    const int lane  = tid & 31;
    const int warpM = wid >> 1;                 // 0..3
    const int warpN = wid & 1;                  // 0..1
    const int n0 = blockIdx.x * 128;
    const int m0 = blockIdx.y * 128;

    if (tid < 128) bs[tid] = bias[n0 + tid];

    // Stage loader: 1024 16B-chunks for A, 1024 for B; 4+4 per thread.
    auto load_stage = [&](int kt, int buf) {
        const uint32_t sb = smem_u32(tile) + (uint32_t)buf * STG_BYTES;
        const float* Xg = X + (size_t)m0 * D_MODEL + kt * KTILE;
        const float* Wg = W + (size_t)n0 * D_MODEL + kt * KTILE;
#pragma unroll
        for (int j = 0; j < 4; j++) {
            const int id  = tid + (j << 8);     // 0..1023
            const int row = id >> 3;            // 0..127
            const int c16 = id & 7;             // 0..7 (16B units)
            const uint32_t off = (uint32_t)(row * LDA * 4 + c16 * 16);
            CP_ASYNC16(sb + off, Xg + (size_t)row * D_MODEL + c16 * 4);
            CP_ASYNC16(sb + 128 * LDA * 4 + off, Wg + (size_t)row * D_MODEL + c16 * 4);
        }
    };

    wmma::fragment<wmma::accumulator, 16, 16, 8, float> c[2][4];
#pragma unroll
    for (int i = 0; i < 2; i++)
#pragma unroll
        for (int j = 0; j < 4; j++) wmma::fill_fragment(c[i][j], 0.0f);

    const int NKT = D_MODEL / KTILE;            // 32
#pragma unroll 1
    for (int s = 0; s < NSTAGE; s++) { load_stage(s, s); CP_COMMIT(); }

#pragma unroll 1
    for (int kt = 0; kt < NKT; kt++) {
        CP_WAIT2();
        __syncthreads();

        const int buf = kt % NSTAGE;
        const float* As = tile + buf * STG_FLT;
        const float* Bs = As + 128 * LDA;

#pragma unroll
        for (int kk = 0; kk < 4; kk++) {
            wmma::fragment<wmma::matrix_a, 16, 16, 8, wmma::precision::tf32, wmma::row_major> a[2];
            wmma::fragment<wmma::matrix_b, 16, 16, 8, wmma::precision::tf32, wmma::col_major> b[4];
#pragma unroll
            for (int i = 0; i < 2; i++)
                wmma::load_matrix_sync(a[i], As + (warpM * 32 + i * 16) * LDA + kk * 8, LDA);
#pragma unroll
            for (int j = 0; j < 4; j++)
                wmma::load_matrix_sync(b[j], Bs + (warpN * 64 + j * 16) * LDA + kk * 8, LDA);
#pragma unroll
            for (int i = 0; i < 2; i++)
#pragma unroll
                for (int j = 0; j < 4; j++)
                    wmma::mma_sync(c[i][j], a[i], b[j], c[i][j]);
        }
        __syncthreads();

        const int nk = kt + NSTAGE;
        if (nk < NKT) load_stage(nk, nk % NSTAGE);
        CP_COMMIT();
    }

    // Epilogue: stage per-warp 32x64 tile in smem, add bias, write float4.
    // FIX (R3 bug): each lane owns ONE full row (r = lane, 0..31) and writes
    // all 64 columns (16 float4) -> full 32x64 = 2048 floats per warp.
    asm volatile("cp.async.wait_group 0;" ::: "memory");
    __syncthreads();
    float* epi = tile + wid * (32 * 64);
#pragma unroll
    for (int i = 0; i < 2; i++)
#pragma unroll
        for (int j = 0; j < 4; j++)
            wmma::store_matrix_sync(epi + i * 16 * 64 + j * 16, c[i][j], 64,
                                    wmma::mem_row_major);
    __syncwarp();

    const int r = lane;                          // 0..31 (one row per lane)
    float* yrow = Y + (size_t)(m0 + warpM * 32 + r) * D_MODEL + n0 + warpN * 64;
    const float* erow = epi + r * 64;
    const float* brow = bs + warpN * 64;
#pragma unroll
    for (int c4 = 0; c4 < 16; c4++) {
        float4 v  = *(const float4*)(erow + c4 * 4);
        float4 bv = *(const float4*)(brow + c4 * 4);
        v.x += bv.x; v.y += bv.y; v.z += bv.z; v.w += bv.w;
        *(float4*)(yrow + c4 * 4) = v;
    }
}

// ---------------------------------------------------------------------------
// Packed f32x2 helpers for the attention kernel
// ---------------------------------------------------------------------------
__device__ __forceinline__ unsigned long long pack2(float x, float y) {
    unsigned long long r;
    asm("mov.b64 %0, {%1, %2};" : "=l"(r) : "f"(x), "f"(y));
    return r;
}
__device__ __forceinline__ float2 unpack2(unsigned long long u) {
    float2 f;
    asm("mov.b64 {%0, %1}, %2;" : "=f"(f.x), "=f"(f.y) : "l"(u));
    return f;
}
__device__ __forceinline__ unsigned long long fma2(unsigned long long a,
                                                   unsigned long long b,
                                                   unsigned long long c) {
    unsigned long long d;
    asm("fma.rn.f32x2 %0, %1, %2, %3;" : "=l"(d) : "l"(a), "l"(b), "l"(c));
    return d;
}
__device__ __forceinline__ unsigned long long mul2(unsigned long long a,
                                                   unsigned long long b) {
    unsigned long long d;
    asm("mul.rn.f32x2 %0, %1, %2;" : "=l"(d) : "l"(a), "l"(b));
    return d;
}

// ---------------------------------------------------------------------------
// Fused attention (flash style, fp32) -- unchanged (passing, R1)
// ---------------------------------------------------------------------------
#define AQ 64
#define AK 32

__global__ __launch_bounds__(256) void attn_kernel(
    const float* __restrict__ Q, const float* __restrict__ K,
    const float* __restrict__ V, float* __restrict__ O)
{
    __shared__ __align__(16) float QsT[DEPTH][AQ + 4];
    __shared__ __align__(16) float Ks [AK][DEPTH + 1];
    __shared__ __align__(16) float Vs [AK][DEPTH];
    __shared__ __align__(16) float Ps [AQ][AK];

    const int tid = threadIdx.x;
    const int tx = tid & 15;
    const int ty = tid >> 4;
    const int q0 = blockIdx.x * AQ;
    const int h  = blockIdx.y;
    const int b  = blockIdx.z;
    const size_t base = ((size_t)b * SEQ) * D_MODEL + (size_t)h * DEPTH;

#pragma unroll
    for (int it = 0; it < 4; it++) {
        const int idx = tid + (it << 8);
        const int r  = idx >> 4;
        const int c4 = (idx & 15) << 2;
        float4 v4 = *(const float4*)&Q[base + (size_t)(q0 + r) * D_MODEL + c4];
        QsT[c4 + 0][r] = v4.x * ATT_SCALE;
        QsT[c4 + 1][r] = v4.y * ATT_SCALE;
        QsT[c4 + 2][r] = v4.z * ATT_SCALE;
        QsT[c4 + 3][r] = v4.w * ATT_SCALE;
    }

    float m_[4], l_[4];
    unsigned long long accO[4][2];
#pragma unroll
    for (int i = 0; i < 4; i++) {
        m_[i] = -3.0e38f; l_[i] = 0.0f;
        accO[i][0] = 0ull; accO[i][1] = 0ull;
    }

    for (int t = 0; t < SEQ / AK; t++) {
        const int kv0 = t * AK;
        __syncthreads();

#pragma unroll
        for (int it = 0; it < 2; it++) {
            const int idx = tid + (it << 8);
            const int r  = idx >> 4;
            const int c4 = (idx & 15) << 2;
            float4 k4 = *(const float4*)&K[base + (size_t)(kv0 + r) * D_MODEL + c4];
            Ks[r][c4 + 0] = k4.x; Ks[r][c4 + 1] = k4.y;
            Ks[r][c4 + 2] = k4.z; Ks[r][c4 + 3] = k4.w;
            float4 v4 = *(const float4*)&V[base + (size_t)(kv0 + r) * D_MODEL + c4];
            *(float4*)&Vs[r][c4] = v4;
        }
        __syncthreads();

        unsigned long long s00 = 0ull, s01 = 0ull, s10 = 0ull, s11 = 0ull;
#pragma unroll 16
        for (int kk = 0; kk < DEPTH; kk++) {
            const ulonglong2 qa = *(const ulonglong2*)&QsT[kk][ty << 2];
            const float b0 = Ks[(tx << 1) + 0][kk];
            const float b1 = Ks[(tx << 1) + 1][kk];
            const unsigned long long bb0 = pack2(b0, b0);
            const unsigned long long bb1 = pack2(b1, b1);
            s00 = fma2(qa.x, bb0, s00); s01 = fma2(qa.y, bb0, s01);
            s10 = fma2(qa.x, bb1, s10); s11 = fma2(qa.y, bb1, s11);
        }
        float sc[4][2];
        { float2 f = unpack2(s00); sc[0][0] = f.x; sc[1][0] = f.y; }
        { float2 f = unpack2(s01); sc[2][0] = f.x; sc[3][0] = f.y; }
        { float2 f = unpack2(s10); sc[0][1] = f.x; sc[1][1] = f.y; }
        { float2 f = unpack2(s11); sc[2][1] = f.x; sc[3][1] = f.y; }

#pragma unroll
        for (int i = 0; i < 4; i++) {
            float tm = fmaxf(sc[i][0], sc[i][1]);
#pragma unroll
            for (int o = 8; o; o >>= 1)
                tm = fmaxf(tm, __shfl_xor_sync(0xffffffffu, tm, o));
            const float mn   = fmaxf(m_[i], tm);
            const float corr = __expf(m_[i] - mn);
            m_[i] = mn;
            const float p0 = __expf(sc[i][0] - mn);
            const float p1 = __expf(sc[i][1] - mn);
            float ts = p0 + p1;
#pragma unroll
            for (int o = 8; o; o >>= 1)
                ts += __shfl_xor_sync(0xffffffffu, ts, o);
            l_[i] = l_[i] * corr + ts;
            const unsigned long long cc = pack2(corr, corr);
            accO[i][0] = mul2(accO[i][0], cc);
            accO[i][1] = mul2(accO[i][1], cc);
            *(float2*)&Ps[(ty << 2) + i][tx << 1] = make_float2(p0, p1);
        }
        __syncthreads();

#pragma unroll 8
        for (int kc = 0; kc < AK; kc++) {
            const ulonglong2 vv = *(const ulonglong2*)&Vs[kc][tx << 2];
#pragma unroll
            for (int i = 0; i < 4; i++) {
                const float a = Ps[(ty << 2) + i][kc];
                const unsigned long long aa = pack2(a, a);
                accO[i][0] = fma2(aa, vv.x, accO[i][0]);
                accO[i][1] = fma2(aa, vv.y, accO[i][1]);
            }
        }
    }

#pragma unroll
    for (int i = 0; i < 4; i++) {
        const float inv = 1.0f / l_[i];
        const float2 lo = unpack2(accO[i][0]);
        const float2 hi = unpack2(accO[i][1]);
        float4 o4 = make_float4(lo.x * inv, lo.y * inv, hi.x * inv, hi.y * inv);
        *(float4*)&O[base + (size_t)(q0 + (ty << 2) + i) * D_MODEL + (tx << 2)] = o4;
    }
}

// ---------------------------------------------------------------------------
// Launch
// ---------------------------------------------------------------------------
extern "C" void kernel_launch(void* const* d_in, const int* in_sizes, int n_in,
                              void* d_out, int out_size)
{
    (void)in_sizes; (void)n_in; (void)out_size;
    const float* v_in = (const float*)d_in[0];
    const float* k_in = (const float*)d_in[1];
    const float* q_in = (const float*)d_in[2];
    const float* wq   = (const float*)d_in[3];
    const float* bq   = (const float*)d_in[4];
    const float* wk   = (const float*)d_in[5];
    const float* bk   = (const float*)d_in[6];
    const float* wv   = (const float*)d_in[7];
    const float* bv   = (const float*)d_in[8];
    const float* wd   = (const float*)d_in[9];
    const float* bd   = (const float*)d_in[10];

    float *pq, *pk, *pv, *po, *xc, *wc;
    cudaGetSymbolAddress((void**)&pq, g_qp);
    cudaGetSymbolAddress((void**)&pk, g_kp);
    cudaGetSymbolAddress((void**)&pv, g_vp);
    cudaGetSymbolAddress((void**)&po, g_op);
    cudaGetSymbolAddress((void**)&xc, g_xc);
    cudaGetSymbolAddress((void**)&wc, g_wc);

    cudaFuncSetAttribute(gemm_wmma_tf32_kernel,
                         cudaFuncAttributeMaxDynamicSharedMemorySize, GEMM_SMEM);

    const int xBlk = (ROWS_TOT * D_MODEL / 4) / 256;   // 8192
    const int wBlk = (D_MODEL * D_MODEL / 4) / 256;    // 1024
    dim3 ggrid(D_MODEL / 128, ROWS_TOT / 128);         // (8, 64)

    // Q projection
    rna_tf32_kernel<<<xBlk, 256>>>((const float4*)q_in, (float4*)xc);
    rna_tf32_kernel<<<wBlk, 256>>>((const float4*)wq, (float4*)wc);
    gemm_wmma_tf32_kernel<<<ggrid, 256, GEMM_SMEM>>>(xc, wc, bq, pq);
    // K projection
    rna_tf32_kernel<<<xBlk, 256>>>((const float4*)k_in, (float4*)xc);
    rna_tf32_kernel<<<wBlk, 256>>>((const float4*)wk, (float4*)wc);
    gemm_wmma_tf32_kernel<<<ggrid, 256, GEMM_SMEM>>>(xc, wc, bk, pk);
    // V projection
    rna_tf32_kernel<<<xBlk, 256>>>((const float4*)v_in, (float4*)xc);
    rna_tf32_kernel<<<wBlk, 256>>>((const float4*)wv, (float4*)wc);
    gemm_wmma_tf32_kernel<<<ggrid, 256, GEMM_SMEM>>>(xc, wc, bv, pv);

    // Attention (fp32)
    attn_kernel<<<dim3(SEQ / AQ, NUM_HEADS, BATCH), 256>>>(pq, pk, pv, po);

    // Dense projection
    rna_tf32_kernel<<<xBlk, 256>>>((const float4*)po, (float4*)xc);
    rna_tf32_kernel<<<wBlk, 256>>>((const float4*)wd, (float4*)wc);
    gemm_wmma_tf32_kernel<<<ggrid, 256, GEMM_SMEM>>>(xc, wc, bd, (float*)d_out);
}

// round 5
// speedup vs baseline: 2.1038x; 1.7762x over previous
#include <cuda_runtime.h>
#include <mma.h>
#include <cstdint>

using namespace nvcuda;

// Problem constants
#define D_MODEL   1024
#define NUM_HEADS 16
#define DEPTH     64
#define BATCH     4
#define SEQ       2048
#define ROWS_TOT  (BATCH * SEQ)   // 8192
#define ATT_SCALE 0.125f          // 1/sqrt(DEPTH) = 2^-3 (tf32-exact scaling)

// ---------------------------------------------------------------------------
// Scratch (device globals -- no allocation allowed)
// ---------------------------------------------------------------------------
__device__ float g_qp[ROWS_TOT * D_MODEL];
__device__ float g_kp[ROWS_TOT * D_MODEL];
__device__ float g_vp[ROWS_TOT * D_MODEL];
__device__ float g_op[ROWS_TOT * D_MODEL];
__device__ float g_xc[ROWS_TOT * D_MODEL];   // tf32-rounded activations
__device__ float g_wc[D_MODEL * D_MODEL];    // tf32-rounded weights

// ---------------------------------------------------------------------------
// Common helpers
// ---------------------------------------------------------------------------
__device__ __forceinline__ uint32_t smem_u32(const void* p) {
    uint32_t a;
    asm("{ .reg .u64 t; cvta.to.shared.u64 t, %1; cvt.u32.u64 %0, t; }"
        : "=r"(a) : "l"(p));
    return a;
}
__device__ __forceinline__ float rna_tf32f(float x) {
    uint32_t u;
    asm("cvt.rna.tf32.f32 %0, %1;" : "=r"(u) : "f"(x));
    return __uint_as_float(u);
}
__device__ __forceinline__ uint32_t rna_tf32u(float x) {
    uint32_t u;
    asm("cvt.rna.tf32.f32 %0, %1;" : "=r"(u) : "f"(x));
    return u;
}

#define CP_ASYNC16(dst, src) \
    asm volatile("cp.async.cg.shared.global [%0], [%1], 16;" :: "r"(dst), "l"(src) : "memory")
#define CP_COMMIT()  asm volatile("cp.async.commit_group;" ::: "memory")
#define CP_WAIT0()   asm volatile("cp.async.wait_group 0;" ::: "memory")
#define CP_WAIT2()   asm volatile("cp.async.wait_group 2;" ::: "memory")

// mma.sync m16n8k8 tf32 (documented fragment layouts)
__device__ __forceinline__ void mma_tf32(float c[4], uint32_t a0, uint32_t a1,
                                         uint32_t a2, uint32_t a3,
                                         uint32_t b0, uint32_t b1) {
    asm volatile(
        "mma.sync.aligned.m16n8k8.row.col.f32.tf32.tf32.f32 "
        "{%0,%1,%2,%3}, {%4,%5,%6,%7}, {%8,%9}, {%0,%1,%2,%3};"
        : "+f"(c[0]), "+f"(c[1]), "+f"(c[2]), "+f"(c[3])
        : "r"(a0), "r"(a1), "r"(a2), "r"(a3), "r"(b0), "r"(b1));
}

// ---------------------------------------------------------------------------
// tf32-rna rounding pass (unbiased tf32 conversion, stored as fp32)
// ---------------------------------------------------------------------------
__global__ void rna_tf32_kernel(const float4* __restrict__ x, float4* __restrict__ y) {
    const int i = blockIdx.x * blockDim.x + threadIdx.x;
    float4 v = x[i];
    float4 o;
    o.x = rna_tf32f(v.x); o.y = rna_tf32f(v.y);
    o.z = rna_tf32f(v.z); o.w = rna_tf32f(v.w);
    y[i] = o;
}

// ---------------------------------------------------------------------------
// wmma tf32 GEMM: Y[m,n] = sum_k X[m,k] * W[n,k] + bias[n]   (x @ W.T + b)
// CTA tile 128x128, K-tile 32, 3-stage cp.async pipeline.
// round_out != 0 -> epilogue rna-rounds outputs to tf32 (feeds attention).
// ---------------------------------------------------------------------------
#define KTILE     32
#define LDA       36
#define STG_FLT   (2 * 128 * LDA)
#define STG_BYTES (STG_FLT * 4)
#define NSTAGE    3
#define GEMM_SMEM (512 + NSTAGE * STG_BYTES)

__global__ __launch_bounds__(256) void gemm_wmma_tf32_kernel(
    const float* __restrict__ X, const float* __restrict__ W,
    const float* __restrict__ bias, float* __restrict__ Y, int round_out)
{
    extern __shared__ char smem[];
    float* bs   = (float*)smem;
    float* tile = (float*)(smem + 512);

    const int tid   = threadIdx.x;
    const int wid   = tid >> 5;
    const int lane  = tid & 31;
    const int warpM = wid >> 1;
    const int warpN = wid & 1;
    const int n0 = blockIdx.x * 128;
    const int m0 = blockIdx.y * 128;

    if (tid < 128) bs[tid] = bias[n0 + tid];

    auto load_stage = [&](int kt, int buf) {
        const uint32_t sb = smem_u32(tile) + (uint32_t)buf * STG_BYTES;
        const float* Xg = X + (size_t)m0 * D_MODEL + kt * KTILE;
        const float* Wg = W + (size_t)n0 * D_MODEL + kt * KTILE;
#pragma unroll
        for (int j = 0; j < 4; j++) {
            const int id  = tid + (j << 8);
            const int row = id >> 3;
            const int c16 = id & 7;
            const uint32_t off = (uint32_t)(row * LDA * 4 + c16 * 16);
            CP_ASYNC16(sb + off, Xg + (size_t)row * D_MODEL + c16 * 4);
            CP_ASYNC16(sb + 128 * LDA * 4 + off, Wg + (size_t)row * D_MODEL + c16 * 4);
        }
    };

    wmma::fragment<wmma::accumulator, 16, 16, 8, float> c[2][4];
#pragma unroll
    for (int i = 0; i < 2; i++)
#pragma unroll
        for (int j = 0; j < 4; j++) wmma::fill_fragment(c[i][j], 0.0f);

    const int NKT = D_MODEL / KTILE;
#pragma unroll 1
    for (int s = 0; s < NSTAGE; s++) { load_stage(s, s); CP_COMMIT(); }

#pragma unroll 1
    for (int kt = 0; kt < NKT; kt++) {
        CP_WAIT2();
        __syncthreads();

        const int buf = kt % NSTAGE;
        const float* As = tile + buf * STG_FLT;
        const float* Bs = As + 128 * LDA;

#pragma unroll
        for (int kk = 0; kk < 4; kk++) {
            wmma::fragment<wmma::matrix_a, 16, 16, 8, wmma::precision::tf32, wmma::row_major> a[2];
            wmma::fragment<wmma::matrix_b, 16, 16, 8, wmma::precision::tf32, wmma::col_major> b[4];
#pragma unroll
            for (int i = 0; i < 2; i++)
                wmma::load_matrix_sync(a[i], As + (warpM * 32 + i * 16) * LDA + kk * 8, LDA);
#pragma unroll
            for (int j = 0; j < 4; j++)
                wmma::load_matrix_sync(b[j], Bs + (warpN * 64 + j * 16) * LDA + kk * 8, LDA);
#pragma unroll
            for (int i = 0; i < 2; i++)
#pragma unroll
                for (int j = 0; j < 4; j++)
                    wmma::mma_sync(c[i][j], a[i], b[j], c[i][j]);
        }
        __syncthreads();

        const int nk = kt + NSTAGE;
        if (nk < NKT) load_stage(nk, nk % NSTAGE);
        CP_COMMIT();
    }

    CP_WAIT0();
    __syncthreads();
    float* epi = tile + wid * (32 * 64);
#pragma unroll
    for (int i = 0; i < 2; i++)
#pragma unroll
        for (int j = 0; j < 4; j++)
            wmma::store_matrix_sync(epi + i * 16 * 64 + j * 16, c[i][j], 64,
                                    wmma::mem_row_major);
    __syncwarp();

    const int r = lane;
    float* yrow = Y + (size_t)(m0 + warpM * 32 + r) * D_MODEL + n0 + warpN * 64;
    const float* erow = epi + r * 64;
    const float* brow = bs + warpN * 64;
#pragma unroll
    for (int c4 = 0; c4 < 16; c4++) {
        float4 v  = *(const float4*)(erow + c4 * 4);
        float4 bv = *(const float4*)(brow + c4 * 4);
        v.x += bv.x; v.y += bv.y; v.z += bv.z; v.w += bv.w;
        if (round_out) {
            v.x = rna_tf32f(v.x); v.y = rna_tf32f(v.y);
            v.z = rna_tf32f(v.z); v.w = rna_tf32f(v.w);
        }
        *(float4*)(yrow + c4 * 4) = v;
    }
}

// ---------------------------------------------------------------------------
// Tensor-core flash attention (mma.sync m16n8k8 tf32, online softmax in regs)
// Block: 128 queries x 1 head, 8 warps x 16 rows. KV tiles of 64 via cp.async.
// Q,K,V are pre-rounded to tf32 by the projection GEMM epilogue.
// Smem layout (floats): Qs[128][68] | Ks[64][68] | Vr[64][72] | Ps[128][68]
// ---------------------------------------------------------------------------
#define LDQ 68
#define LDK 68
#define LDV 72
#define LDP 68
#define OFF_KS  (128 * LDQ)            // 8704
#define OFF_VR  (OFF_KS + 64 * LDK)    // 13056
#define OFF_PS  (OFF_VR + 64 * LDV)    // 17664
#define ATTN_SMEM ((OFF_PS + 128 * LDP) * 4)   // 105472 bytes

__global__ __launch_bounds__(256, 2) void attn_mma_kernel(
    const float* __restrict__ Q, const float* __restrict__ K,
    const float* __restrict__ V, float* __restrict__ O)
{
    extern __shared__ float sm[];
    float* Qs = sm;
    float* Ks = sm + OFF_KS;
    float* Vr = sm + OFF_VR;
    float* Ps = sm + OFF_PS;
    const uint32_t QsU = smem_u32(Qs);
    const uint32_t KsU = smem_u32(Ks);
    const uint32_t VrU = smem_u32(Vr);
    const uint32_t PsU = smem_u32(Ps);

    const int tid  = threadIdx.x;
    const int wid  = tid >> 5;
    const int lane = tid & 31;
    const int g = lane >> 2;        // groupID
    const int t = lane & 3;         // threadID_in_group
    const int q0 = blockIdx.x * 128;
    const int h  = blockIdx.y;
    const int b  = blockIdx.z;
    const size_t base = (size_t)b * SEQ * D_MODEL + (size_t)h * DEPTH;

    const int row0 = wid * 16 + g;  // warp rows: row0 and row0+8
    const int row1 = row0 + 8;

    // ---- Prologue: load + scale Q tile (128x64) into Qs ----
#pragma unroll
    for (int j = 0; j < 8; j++) {
        const int id = tid + (j << 8);
        const int r  = id >> 4;
        const int c4 = (id & 15) << 2;
        float4 v = *(const float4*)&Q[base + (size_t)(q0 + r) * D_MODEL + c4];
        v.x *= ATT_SCALE; v.y *= ATT_SCALE; v.z *= ATT_SCALE; v.w *= ATT_SCALE;
        *(float4*)&Qs[r * LDQ + c4] = v;
    }

    float m0 = -3.0e38f, m1 = -3.0e38f, l0 = 0.0f, l1 = 0.0f;
    float o[8][4];
#pragma unroll
    for (int j = 0; j < 8; j++) { o[j][0] = o[j][1] = o[j][2] = o[j][3] = 0.0f; }

    const float* Kg = K + base;
    const float* Vg = V + base;

#pragma unroll 1
    for (int kt = 0; kt < SEQ / 64; kt++) {
        __syncthreads();            // prev tile fully consumed (also covers Qs at kt=0)

        // ---- cp.async K/V tile (64 x 64) ----
        const int kv0 = kt * 64;
#pragma unroll
        for (int j = 0; j < 4; j++) {
            const int id  = tid + (j << 8);
            const int r   = id >> 4;
            const int c16 = id & 15;
            CP_ASYNC16(KsU + (uint32_t)(r * LDK * 4 + c16 * 16),
                       Kg + (size_t)(kv0 + r) * D_MODEL + c16 * 4);
            CP_ASYNC16(VrU + (uint32_t)(r * LDV * 4 + c16 * 16),
                       Vg + (size_t)(kv0 + r) * D_MODEL + c16 * 4);
        }
        CP_COMMIT();
        CP_WAIT0();
        __syncthreads();

        // ---- S = Q * K^T : warp computes 16 x 64 in 8 n-frags ----
        float s[8][4];
#pragma unroll
        for (int j = 0; j < 8; j++) { s[j][0] = s[j][1] = s[j][2] = s[j][3] = 0.0f; }

#pragma unroll
        for (int kc = 0; kc < 8; kc++) {
            uint32_t a0, a1, a2, a3;
            asm volatile("ld.shared.b32 %0, [%1];" : "=r"(a0) : "r"(QsU + (row0 * LDQ + kc * 8 + t) * 4));
            asm volatile("ld.shared.b32 %0, [%1];" : "=r"(a1) : "r"(QsU + (row1 * LDQ + kc * 8 + t) * 4));
            asm volatile("ld.shared.b32 %0, [%1];" : "=r"(a2) : "r"(QsU + (row0 * LDQ + kc * 8 + t + 4) * 4));
            asm volatile("ld.shared.b32 %0, [%1];" : "=r"(a3) : "r"(QsU + (row1 * LDQ + kc * 8 + t + 4) * 4));
#pragma unroll
            for (int j = 0; j < 8; j++) {
                uint32_t b0, b1;
                asm volatile("ld.shared.b32 %0, [%1];" : "=r"(b0) : "r"(KsU + ((8 * j + g) * LDK + kc * 8 + t) * 4));
                asm volatile("ld.shared.b32 %0, [%1];" : "=r"(b1) : "r"(KsU + ((8 * j + g) * LDK + kc * 8 + t + 4) * 4));
                mma_tf32(s[j], a0, a1, a2, a3, b0, b1);
            }
        }

        // ---- online softmax (rows row0, row1; stats shared across 4 lanes) ----
        float tm0 = fmaxf(s[0][0], s[0][1]);
        float tm1 = fmaxf(s[0][2], s[0][3]);
#pragma unroll
        for (int j = 1; j < 8; j++) {
            tm0 = fmaxf(tm0, fmaxf(s[j][0], s[j][1]));
            tm1 = fmaxf(tm1, fmaxf(s[j][2], s[j][3]));
        }
        tm0 = fmaxf(tm0, __shfl_xor_sync(0xffffffffu, tm0, 1));
        tm0 = fmaxf(tm0, __shfl_xor_sync(0xffffffffu, tm0, 2));
        tm1 = fmaxf(tm1, __shfl_xor_sync(0xffffffffu, tm1, 1));
        tm1 = fmaxf(tm1, __shfl_xor_sync(0xffffffffu, tm1, 2));

        const float mn0 = fmaxf(m0, tm0);
        const float mn1 = fmaxf(m1, tm1);
        const float corr0 = __expf(m0 - mn0);
        const float corr1 = __expf(m1 - mn1);
        m0 = mn0; m1 = mn1;

        float sum0 = 0.0f, sum1 = 0.0f;
#pragma unroll
        for (int j = 0; j < 8; j++) {
            const float p00 = __expf(s[j][0] - mn0);
            const float p01 = __expf(s[j][1] - mn0);
            const float p10 = __expf(s[j][2] - mn1);
            const float p11 = __expf(s[j][3] - mn1);
            sum0 += p00 + p01;
            sum1 += p10 + p11;
            uint2 w0 = make_uint2(rna_tf32u(p00), rna_tf32u(p01));
            uint2 w1 = make_uint2(rna_tf32u(p10), rna_tf32u(p11));
            asm volatile("st.shared.v2.b32 [%0], {%1, %2};" ::
                         "r"(PsU + (row0 * LDP + 8 * j + 2 * t) * 4), "r"(w0.x), "r"(w0.y) : "memory");
            asm volatile("st.shared.v2.b32 [%0], {%1, %2};" ::
                         "r"(PsU + (row1 * LDP + 8 * j + 2 * t) * 4), "r"(w1.x), "r"(w1.y) : "memory");
        }
        sum0 += __shfl_xor_sync(0xffffffffu, sum0, 1);
        sum0 += __shfl_xor_sync(0xffffffffu, sum0, 2);
        sum1 += __shfl_xor_sync(0xffffffffu, sum1, 1);
        sum1 += __shfl_xor_sync(0xffffffffu, sum1, 2);
        l0 = l0 * corr0 + sum0;
        l1 = l1 * corr1 + sum1;
#pragma unroll
        for (int j = 0; j < 8; j++) {
            o[j][0] *= corr0; o[j][1] *= corr0;
            o[j][2] *= corr1; o[j][3] *= corr1;
        }
        __syncwarp();

        // ---- O += P * V : A = P (16 x 64 kv), B = V (kv x depth via direct idx) ----
#pragma unroll
        for (int kc = 0; kc < 8; kc++) {
            uint32_t a0, a1, a2, a3;
            asm volatile("ld.shared.b32 %0, [%1];" : "=r"(a0) : "r"(PsU + (row0 * LDP + kc * 8 + t) * 4));
            asm volatile("ld.shared.b32 %0, [%1];" : "=r"(a1) : "r"(PsU + (row1 * LDP + kc * 8 + t) * 4));
            asm volatile("ld.shared.b32 %0, [%1];" : "=r"(a2) : "r"(PsU + (row0 * LDP + kc * 8 + t + 4) * 4));
            asm volatile("ld.shared.b32 %0, [%1];" : "=r"(a3) : "r"(PsU + (row1 * LDP + kc * 8 + t + 4) * 4));
#pragma unroll
            for (int j = 0; j < 8; j++) {
                uint32_t b0, b1;
                asm volatile("ld.shared.b32 %0, [%1];" : "=r"(b0) : "r"(VrU + ((kc * 8 + t) * LDV + 8 * j + g) * 4));
                asm volatile("ld.shared.b32 %0, [%1];" : "=r"(b1) : "r"(VrU + ((kc * 8 + t + 4) * LDV + 8 * j + g) * 4));
                mma_tf32(o[j], a0, a1, a2, a3, b0, b1);
            }
        }
    }

    // ---- Epilogue: normalize and write ----
    const float inv0 = 1.0f / l0;
    const float inv1 = 1.0f / l1;
    float* or0 = O + base + (size_t)(q0 + row0) * D_MODEL;
    float* or1 = O + base + (size_t)(q0 + row1) * D_MODEL;
#pragma unroll
    for (int j = 0; j < 8; j++) {
        *(float2*)(or0 + 8 * j + 2 * t) = make_float2(o[j][0] * inv0, o[j][1] * inv0);
        *(float2*)(or1 + 8 * j + 2 * t) = make_float2(o[j][2] * inv1, o[j][3] * inv1);
    }
}

// ---------------------------------------------------------------------------
// Launch
// ---------------------------------------------------------------------------
extern "C" void kernel_launch(void* const* d_in, const int* in_sizes, int n_in,
                              void* d_out, int out_size)
{
    (void)in_sizes; (void)n_in; (void)out_size;
    const float* v_in = (const float*)d_in[0];
    const float* k_in = (const float*)d_in[1];
    const float* q_in = (const float*)d_in[2];
    const float* wq   = (const float*)d_in[3];
    const float* bq   = (const float*)d_in[4];
    const float* wk   = (const float*)d_in[5];
    const float* bk   = (const float*)d_in[6];
    const float* wv   = (const float*)d_in[7];
    const float* bv   = (const float*)d_in[8];
    const float* wd   = (const float*)d_in[9];
    const float* bd   = (const float*)d_in[10];

    float *pq, *pk, *pv, *po, *xc, *wc;
    cudaGetSymbolAddress((void**)&pq, g_qp);
    cudaGetSymbolAddress((void**)&pk, g_kp);
    cudaGetSymbolAddress((void**)&pv, g_vp);
    cudaGetSymbolAddress((void**)&po, g_op);
    cudaGetSymbolAddress((void**)&xc, g_xc);
    cudaGetSymbolAddress((void**)&wc, g_wc);

    cudaFuncSetAttribute(gemm_wmma_tf32_kernel,
                         cudaFuncAttributeMaxDynamicSharedMemorySize, GEMM_SMEM);
    cudaFuncSetAttribute(attn_mma_kernel,
                         cudaFuncAttributeMaxDynamicSharedMemorySize, ATTN_SMEM);

    const int xBlk = (ROWS_TOT * D_MODEL / 4) / 256;   // 8192
    const int wBlk = (D_MODEL * D_MODEL / 4) / 256;    // 1024
    dim3 ggrid(D_MODEL / 128, ROWS_TOT / 128);         // (8, 64)

    // Q projection (outputs rna-tf32-rounded for the attention mma)
    rna_tf32_kernel<<<xBlk, 256>>>((const float4*)q_in, (float4*)xc);
    rna_tf32_kernel<<<wBlk, 256>>>((const float4*)wq, (float4*)wc);
    gemm_wmma_tf32_kernel<<<ggrid, 256, GEMM_SMEM>>>(xc, wc, bq, pq, 1);
    // K projection
    rna_tf32_kernel<<<xBlk, 256>>>((const float4*)k_in, (float4*)xc);
    rna_tf32_kernel<<<wBlk, 256>>>((const float4*)wk, (float4*)wc);
    gemm_wmma_tf32_kernel<<<ggrid, 256, GEMM_SMEM>>>(xc, wc, bk, pk, 1);
    // V projection
    rna_tf32_kernel<<<xBlk, 256>>>((const float4*)v_in, (float4*)xc);
    rna_tf32_kernel<<<wBlk, 256>>>((const float4*)wv, (float4*)wc);
    gemm_wmma_tf32_kernel<<<ggrid, 256, GEMM_SMEM>>>(xc, wc, bv, pv, 1);

    // Tensor-core attention
    attn_mma_kernel<<<dim3(SEQ / 128, NUM_HEADS, BATCH), 256, ATTN_SMEM>>>(pq, pk, pv, po);

    // Dense projection (plain fp32 output)
    rna_tf32_kernel<<<xBlk, 256>>>((const float4*)po, (float4*)xc);
    rna_tf32_kernel<<<wBlk, 256>>>((const float4*)wd, (float4*)wc);
    gemm_wmma_tf32_kernel<<<ggrid, 256, GEMM_SMEM>>>(xc, wc, bd, (float*)d_out, 0);
}

// round 8
// speedup vs baseline: 3.6174x; 1.7195x over previous
#include <cuda_runtime.h>
#include <cstdint>

// Problem constants
#define D_MODEL   1024
#define NUM_HEADS 16
#define DEPTH     64
#define BATCH     4
#define SEQ       2048
#define ROWS_TOT  (BATCH * SEQ)   // 8192
#define ATT_SCALE 0.125f          // 1/sqrt(DEPTH) = 2^-3 (tf32-exact scaling)

// ---------------------------------------------------------------------------
// Scratch (device globals -- no allocation allowed)
// ---------------------------------------------------------------------------
__device__ float g_qp[ROWS_TOT * D_MODEL];
__device__ float g_kp[ROWS_TOT * D_MODEL];
__device__ float g_vp[ROWS_TOT * D_MODEL];
__device__ float g_op[ROWS_TOT * D_MODEL];
__device__ float g_xc[ROWS_TOT * D_MODEL];   // tf32-rounded activations
__device__ float g_wc[D_MODEL * D_MODEL];    // tf32-rounded weights

// ---------------------------------------------------------------------------
// Common helpers
// ---------------------------------------------------------------------------
__device__ __forceinline__ uint32_t smem_u32(const void* p) {
    uint32_t a;
    asm("{ .reg .u64 t; cvta.to.shared.u64 t, %1; cvt.u32.u64 %0, t; }"
        : "=r"(a) : "l"(p));
    return a;
}
__device__ __forceinline__ float rna_tf32f(float x) {
    uint32_t u;
    asm("cvt.rna.tf32.f32 %0, %1;" : "=r"(u) : "f"(x));
    return __uint_as_float(u);
}
__device__ __forceinline__ uint32_t rna_tf32u(float x) {
    uint32_t u;
    asm("cvt.rna.tf32.f32 %0, %1;" : "=r"(u) : "f"(x));
    return u;
}

#define CP_ASYNC16(dst, src) \
    asm volatile("cp.async.cg.shared.global [%0], [%1], 16;" :: "r"(dst), "l"(src) : "memory")
#define CP_COMMIT()  asm volatile("cp.async.commit_group;" ::: "memory")
#define CP_WAIT0()   asm volatile("cp.async.wait_group 0;" ::: "memory")
#define CP_WAIT2()   asm volatile("cp.async.wait_group 2;" ::: "memory")

// mma.sync m16n8k8 tf32 (documented fragment layouts; proven in attention)
__device__ __forceinline__ void mma_tf32(float c[4], uint32_t a0, uint32_t a1,
                                         uint32_t a2, uint32_t a3,
                                         uint32_t b0, uint32_t b1) {
    asm volatile(
        "mma.sync.aligned.m16n8k8.row.col.f32.tf32.tf32.f32 "
        "{%0,%1,%2,%3}, {%4,%5,%6,%7}, {%8,%9}, {%0,%1,%2,%3};"
        : "+f"(c[0]), "+f"(c[1]), "+f"(c[2]), "+f"(c[3])
        : "r"(a0), "r"(a1), "r"(a2), "r"(a3), "r"(b0), "r"(b1));
}

// ---------------------------------------------------------------------------
// tf32-rna rounding pass
// ---------------------------------------------------------------------------
__global__ void rna_tf32_kernel(const float4* __restrict__ x, float4* __restrict__ y) {
    const int i = blockIdx.x * blockDim.x + threadIdx.x;
    float4 v = x[i];
    float4 o;
    o.x = rna_tf32f(v.x); o.y = rna_tf32f(v.y);
    o.z = rna_tf32f(v.z); o.w = rna_tf32f(v.w);
    y[i] = o;
}

// ---------------------------------------------------------------------------
// mma.sync tf32 GEMM: Y[m,n] = sum_k X[m,k] * W[n,k] + bias[n]  (x @ W.T + b)
// CTA tile 128x256, warp tile 64x64 (2x4 warp grid), K-tile 32, 3 stages.
// Smem rows padded to LD=36 floats (36 mod 32 = 4 -> frag lanes hit banks
// 4g+t, all distinct -> conflict-free LDS.32 fragment loads).
// ---------------------------------------------------------------------------
#define GM 128
#define GN 256
#define GK 32
#define GLD 36
#define A_FLT (GM * GLD)                 // 4608
#define B_FLT (GN * GLD)                 // 9216
#define STG_FLT (A_FLT + B_FLT)          // 13824
#define GSTG 3
#define GEMM_SMEM (GSTG * STG_FLT * 4)   // 165888 bytes
#define NKT (D_MODEL / GK)               // 32

__global__ __launch_bounds__(256) void gemm_mma_tf32_kernel(
    const float* __restrict__ X, const float* __restrict__ W,
    const float* __restrict__ bias, float* __restrict__ Y, int round_out)
{
    extern __shared__ float sm[];
    const int tid  = threadIdx.x;
    const int wid  = tid >> 5;
    const int lane = tid & 31;
    const int g = lane >> 2;
    const int t = lane & 3;
    const int warpM = wid >> 2;          // 0..1
    const int warpN = wid & 3;           // 0..3
    const int n0 = blockIdx.x * GN;
    const int m0 = blockIdx.y * GM;

    auto load_stage = [&](int kt, int buf) {
        const uint32_t AsU = smem_u32(sm) + (uint32_t)(buf * STG_FLT) * 4;
        const uint32_t BsU = AsU + A_FLT * 4;
        const float* Xg = X + (size_t)m0 * D_MODEL + kt * GK;
        const float* Wg = W + (size_t)n0 * D_MODEL + kt * GK;
#pragma unroll
        for (int j = 0; j < 4; j++) {          // A: 128 rows x 8 chunks
            const int id = tid + (j << 8);
            const int row = id >> 3, cc = id & 7;
            CP_ASYNC16(AsU + (uint32_t)((row * GLD + cc * 4) * 4),
                       Xg + (size_t)row * D_MODEL + cc * 4);
        }
#pragma unroll
        for (int j = 0; j < 8; j++) {          // B: 256 rows x 8 chunks
            const int id = tid + (j << 8);
            const int row = id >> 3, cc = id & 7;
            CP_ASYNC16(BsU + (uint32_t)((row * GLD + cc * 4) * 4),
                       Wg + (size_t)row * D_MODEL + cc * 4);
        }
    };

    float acc[4][8][4];
#pragma unroll
    for (int mi = 0; mi < 4; mi++)
#pragma unroll
        for (int nj = 0; nj < 8; nj++) {
            acc[mi][nj][0] = 0.0f; acc[mi][nj][1] = 0.0f;
            acc[mi][nj][2] = 0.0f; acc[mi][nj][3] = 0.0f;
        }

#pragma unroll 1
    for (int s = 0; s < GSTG; s++) { load_stage(s, s); CP_COMMIT(); }

#pragma unroll 1
    for (int kt = 0; kt < NKT; kt++) {
        CP_WAIT2();
        __syncthreads();

        const float* As = sm + (kt % GSTG) * STG_FLT;
        const float* Bs = As + A_FLT;
        const float* Abase = As + (warpM * 64 + g) * GLD + t;
        const float* Bbase = Bs + (warpN * 64 + g) * GLD + t;

#pragma unroll
        for (int kc = 0; kc < 4; kc++) {
            uint32_t a[4][4], b[8][2];
#pragma unroll
            for (int mi = 0; mi < 4; mi++) {
                const float* ap = Abase + mi * (16 * GLD) + kc * 8;
                a[mi][0] = __float_as_uint(ap[0]);
                a[mi][1] = __float_as_uint(ap[8 * GLD]);
                a[mi][2] = __float_as_uint(ap[4]);
                a[mi][3] = __float_as_uint(ap[8 * GLD + 4]);
            }
#pragma unroll
            for (int nj = 0; nj < 8; nj++) {
                const float* bp = Bbase + nj * (8 * GLD) + kc * 8;
                b[nj][0] = __float_as_uint(bp[0]);
                b[nj][1] = __float_as_uint(bp[4]);
            }
#pragma unroll
            for (int mi = 0; mi < 4; mi++)
#pragma unroll
                for (int nj = 0; nj < 8; nj++)
                    mma_tf32(acc[mi][nj], a[mi][0], a[mi][1], a[mi][2], a[mi][3],
                             b[nj][0], b[nj][1]);
        }
        __syncthreads();

        const int nk = kt + GSTG;
        if (nk < NKT) load_stage(nk, nk % GSTG);
        CP_COMMIT();
    }

    // Epilogue: direct float2 stores from C fragments (+bias, optional rna)
    float2 bv[8];
#pragma unroll
    for (int nj = 0; nj < 8; nj++)
        bv[nj] = *(const float2*)&bias[n0 + warpN * 64 + nj * 8 + 2 * t];

#pragma unroll
    for (int mi = 0; mi < 4; mi++) {
        const int r0 = m0 + warpM * 64 + mi * 16 + g;
        float* y0 = Y + (size_t)r0 * D_MODEL + n0 + warpN * 64 + 2 * t;
        float* y1 = y0 + (size_t)8 * D_MODEL;
#pragma unroll
        for (int nj = 0; nj < 8; nj++) {
            float2 v0 = make_float2(acc[mi][nj][0] + bv[nj].x, acc[mi][nj][1] + bv[nj].y);
            float2 v1 = make_float2(acc[mi][nj][2] + bv[nj].x, acc[mi][nj][3] + bv[nj].y);
            if (round_out) {
                v0.x = rna_tf32f(v0.x); v0.y = rna_tf32f(v0.y);
                v1.x = rna_tf32f(v1.x); v1.y = rna_tf32f(v1.y);
            }
            *(float2*)(y0 + nj * 8) = v0;
            *(float2*)(y1 + nj * 8) = v1;
        }
    }
}

// ---------------------------------------------------------------------------
// Tensor-core flash attention (mma.sync m16n8k8 tf32) -- passing in R5.
// Epilogue emits rna-tf32-rounded O (dense GEMM skips its rna pass).
// ---------------------------------------------------------------------------
#define LDQ 68
#define LDK 68
#define LDV 72
#define LDP 68
#define OFF_KS  (128 * LDQ)
#define OFF_VR  (OFF_KS + 64 * LDK)
#define OFF_PS  (OFF_VR + 64 * LDV)
#define ATTN_SMEM ((OFF_PS + 128 * LDP) * 4)

__global__ __launch_bounds__(256, 2) void attn_mma_kernel(
    const float* __restrict__ Q, const float* __restrict__ K,
    const float* __restrict__ V, float* __restrict__ O)
{
    extern __shared__ float smA[];
    float* Qs = smA;
    const uint32_t QsU = smem_u32(Qs);
    const uint32_t KsU = QsU + OFF_KS * 4;
    const uint32_t VrU = QsU + OFF_VR * 4;
    const uint32_t PsU = QsU + OFF_PS * 4;

    const int tid  = threadIdx.x;
    const int wid  = tid >> 5;
    const int lane = tid & 31;
    const int g = lane >> 2;
    const int t = lane & 3;
    const int q0 = blockIdx.x * 128;
    const int h  = blockIdx.y;
    const int b  = blockIdx.z;
    const size_t base = (size_t)b * SEQ * D_MODEL + (size_t)h * DEPTH;

    const int row0 = wid * 16 + g;
    const int row1 = row0 + 8;

#pragma unroll
    for (int j = 0; j < 8; j++) {
        const int id = tid + (j << 8);
        const int r  = id >> 4;
        const int c4 = (id & 15) << 2;
        float4 v = *(const float4*)&Q[base + (size_t)(q0 + r) * D_MODEL + c4];
        v.x *= ATT_SCALE; v.y *= ATT_SCALE; v.z *= ATT_SCALE; v.w *= ATT_SCALE;
        *(float4*)&Qs[r * LDQ + c4] = v;
    }

    float m0 = -3.0e38f, m1 = -3.0e38f, l0 = 0.0f, l1 = 0.0f;
    float o[8][4];
#pragma unroll
    for (int j = 0; j < 8; j++) { o[j][0] = o[j][1] = o[j][2] = o[j][3] = 0.0f; }

    const float* Kg = K + base;
    const float* Vg = V + base;

#pragma unroll 1
    for (int kt = 0; kt < SEQ / 64; kt++) {
        __syncthreads();

        const int kv0 = kt * 64;
#pragma unroll
        for (int j = 0; j < 4; j++) {
            const int id  = tid + (j << 8);
            const int r   = id >> 4;
            const int c16 = id & 15;
            CP_ASYNC16(KsU + (uint32_t)(r * LDK * 4 + c16 * 16),
                       Kg + (size_t)(kv0 + r) * D_MODEL + c16 * 4);
            CP_ASYNC16(VrU + (uint32_t)(r * LDV * 4 + c16 * 16),
                       Vg + (size_t)(kv0 + r) * D_MODEL + c16 * 4);
        }
        CP_COMMIT();
        CP_WAIT0();
        __syncthreads();

        float s[8][4];
#pragma unroll
        for (int j = 0; j < 8; j++) { s[j][0] = s[j][1] = s[j][2] = s[j][3] = 0.0f; }

#pragma unroll
        for (int kc = 0; kc < 8; kc++) {
            uint32_t a0, a1, a2, a3;
            asm volatile("ld.shared.b32 %0, [%1];" : "=r"(a0) : "r"(QsU + (row0 * LDQ + kc * 8 + t) * 4));
            asm volatile("ld.shared.b32 %0, [%1];" : "=r"(a1) : "r"(QsU + (row1 * LDQ + kc * 8 + t) * 4));
            asm volatile("ld.shared.b32 %0, [%1];" : "=r"(a2) : "r"(QsU + (row0 * LDQ + kc * 8 + t + 4) * 4));
            asm volatile("ld.shared.b32 %0, [%1];" : "=r"(a3) : "r"(QsU + (row1 * LDQ + kc * 8 + t + 4) * 4));
#pragma unroll
            for (int j = 0; j < 8; j++) {
                uint32_t b0, b1;
                asm volatile("ld.shared.b32 %0, [%1];" : "=r"(b0) : "r"(KsU + ((8 * j + g) * LDK + kc * 8 + t) * 4));
                asm volatile("ld.shared.b32 %0, [%1];" : "=r"(b1) : "r"(KsU + ((8 * j + g) * LDK + kc * 8 + t + 4) * 4));
                mma_tf32(s[j], a0, a1, a2, a3, b0, b1);
            }
        }

        float tm0 = fmaxf(s[0][0], s[0][1]);
        float tm1 = fmaxf(s[0][2], s[0][3]);
#pragma unroll
        for (int j = 1; j < 8; j++) {
            tm0 = fmaxf(tm0, fmaxf(s[j][0], s[j][1]));
            tm1 = fmaxf(tm1, fmaxf(s[j][2], s[j][3]));
        }
        tm0 = fmaxf(tm0, __shfl_xor_sync(0xffffffffu, tm0, 1));
        tm0 = fmaxf(tm0, __shfl_xor_sync(0xffffffffu, tm0, 2));
        tm1 = fmaxf(tm1, __shfl_xor_sync(0xffffffffu, tm1, 1));
        tm1 = fmaxf(tm1, __shfl_xor_sync(0xffffffffu, tm1, 2));

        const float mn0 = fmaxf(m0, tm0);
        const float mn1 = fmaxf(m1, tm1);
        const float corr0 = __expf(m0 - mn0);
        const float corr1 = __expf(m1 - mn1);
        m0 = mn0; m1 = mn1;

        float sum0 = 0.0f, sum1 = 0.0f;
#pragma unroll
        for (int j = 0; j < 8; j++) {
            const float p00 = __expf(s[j][0] - mn0);
            const float p01 = __expf(s[j][1] - mn0);
            const float p10 = __expf(s[j][2] - mn1);
            const float p11 = __expf(s[j][3] - mn1);
            sum0 += p00 + p01;
            sum1 += p10 + p11;
            uint2 w0 = make_uint2(rna_tf32u(p00), rna_tf32u(p01));
            uint2 w1 = make_uint2(rna_tf32u(p10), rna_tf32u(p11));
            asm volatile("st.shared.v2.b32 [%0], {%1, %2};" ::
                         "r"(PsU + (row0 * LDP + 8 * j + 2 * t) * 4), "r"(w0.x), "r"(w0.y) : "memory");
            asm volatile("st.shared.v2.b32 [%0], {%1, %2};" ::
                         "r"(PsU + (row1 * LDP + 8 * j + 2 * t) * 4), "r"(w1.x), "r"(w1.y) : "memory");
        }
        sum0 += __shfl_xor_sync(0xffffffffu, sum0, 1);
        sum0 += __shfl_xor_sync(0xffffffffu, sum0, 2);
        sum1 += __shfl_xor_sync(0xffffffffu, sum1, 1);
        sum1 += __shfl_xor_sync(0xffffffffu, sum1, 2);
        l0 = l0 * corr0 + sum0;
        l1 = l1 * corr1 + sum1;
#pragma unroll
        for (int j = 0; j < 8; j++) {
            o[j][0] *= corr0; o[j][1] *= corr0;
            o[j][2] *= corr1; o[j][3] *= corr1;
        }
        __syncwarp();

#pragma unroll
        for (int kc = 0; kc < 8; kc++) {
            uint32_t a0, a1, a2, a3;
            asm volatile("ld.shared.b32 %0, [%1];" : "=r"(a0) : "r"(PsU + (row0 * LDP + kc * 8 + t) * 4));
            asm volatile("ld.shared.b32 %0, [%1];" : "=r"(a1) : "r"(PsU + (row1 * LDP + kc * 8 + t) * 4));
            asm volatile("ld.shared.b32 %0, [%1];" : "=r"(a2) : "r"(PsU + (row0 * LDP + kc * 8 + t + 4) * 4));
            asm volatile("ld.shared.b32 %0, [%1];" : "=r"(a3) : "r"(PsU + (row1 * LDP + kc * 8 + t + 4) * 4));
#pragma unroll
            for (int j = 0; j < 8; j++) {
                uint32_t b0, b1;
                asm volatile("ld.shared.b32 %0, [%1];" : "=r"(b0) : "r"(VrU + ((kc * 8 + t) * LDV + 8 * j + g) * 4));
                asm volatile("ld.shared.b32 %0, [%1];" : "=r"(b1) : "r"(VrU + ((kc * 8 + t + 4) * LDV + 8 * j + g) * 4));
                mma_tf32(o[j], a0, a1, a2, a3, b0, b1);
            }
        }
    }

    const float inv0 = 1.0f / l0;
    const float inv1 = 1.0f / l1;
    float* or0 = O + base + (size_t)(q0 + row0) * D_MODEL;
    float* or1 = O + base + (size_t)(q0 + row1) * D_MODEL;
#pragma unroll
    for (int j = 0; j < 8; j++) {
        *(float2*)(or0 + 8 * j + 2 * t) =
            make_float2(rna_tf32f(o[j][0] * inv0), rna_tf32f(o[j][1] * inv0));
        *(float2*)(or1 + 8 * j + 2 * t) =
            make_float2(rna_tf32f(o[j][2] * inv1), rna_tf32f(o[j][3] * inv1));
    }
}

// ---------------------------------------------------------------------------
// Launch
// ---------------------------------------------------------------------------
extern "C" void kernel_launch(void* const* d_in, const int* in_sizes, int n_in,
                              void* d_out, int out_size)
{
    (void)in_sizes; (void)n_in; (void)out_size;
    const float* v_in = (const float*)d_in[0];
    const float* k_in = (const float*)d_in[1];
    const float* q_in = (const float*)d_in[2];
    const float* wq   = (const float*)d_in[3];
    const float* bq   = (const float*)d_in[4];
    const float* wk   = (const float*)d_in[5];
    const float* bk   = (const float*)d_in[6];
    const float* wv   = (const float*)d_in[7];
    const float* bv   = (const float*)d_in[8];
    const float* wd   = (const float*)d_in[9];
    const float* bd   = (const float*)d_in[10];

    float *pq, *pk, *pv, *po, *xc, *wc;
    cudaGetSymbolAddress((void**)&pq, g_qp);
    cudaGetSymbolAddress((void**)&pk, g_kp);
    cudaGetSymbolAddress((void**)&pv, g_vp);
    cudaGetSymbolAddress((void**)&po, g_op);
    cudaGetSymbolAddress((void**)&xc, g_xc);
    cudaGetSymbolAddress((void**)&wc, g_wc);

    cudaFuncSetAttribute(gemm_mma_tf32_kernel,
                         cudaFuncAttributeMaxDynamicSharedMemorySize, GEMM_SMEM);
    cudaFuncSetAttribute(attn_mma_kernel,
                         cudaFuncAttributeMaxDynamicSharedMemorySize, ATTN_SMEM);

    const int xBlk = (ROWS_TOT * D_MODEL / 4) / 256;   // 8192
    const int wBlk = (D_MODEL * D_MODEL / 4) / 256;    // 1024
    dim3 ggrid(D_MODEL / GN, ROWS_TOT / GM);           // (4, 64)

    // Q projection (rna-tf32 output for attention)
    rna_tf32_kernel<<<xBlk, 256>>>((const float4*)q_in, (float4*)xc);
    rna_tf32_kernel<<<wBlk, 256>>>((const float4*)wq, (float4*)wc);
    gemm_mma_tf32_kernel<<<ggrid, 256, GEMM_SMEM>>>(xc, wc, bq, pq, 1);
    // K projection
    rna_tf32_kernel<<<xBlk, 256>>>((const float4*)k_in, (float4*)xc);
    rna_tf32_kernel<<<wBlk, 256>>>((const float4*)wk, (float4*)wc);
    gemm_mma_tf32_kernel<<<ggrid, 256, GEMM_SMEM>>>(xc, wc, bk, pk, 1);
    // V projection
    rna_tf32_kernel<<<xBlk, 256>>>((const float4*)v_in, (float4*)xc);
    rna_tf32_kernel<<<wBlk, 256>>>((const float4*)wv, (float4*)wc);
    gemm_mma_tf32_kernel<<<ggrid, 256, GEMM_SMEM>>>(xc, wc, bv, pv, 1);

    // Tensor-core attention (emits rna-rounded O)
    attn_mma_kernel<<<dim3(SEQ / 128, NUM_HEADS, BATCH), 256, ATTN_SMEM>>>(pq, pk, pv, po);

    // Dense projection (po already tf32-rounded; no extra rna pass)
    rna_tf32_kernel<<<wBlk, 256>>>((const float4*)wd, (float4*)wc);
    gemm_mma_tf32_kernel<<<ggrid, 256, GEMM_SMEM>>>(po, wc, bd, (float*)d_out, 0);
}